// round 10
// baseline (speedup 1.0000x reference)
#include <cuda_runtime.h>
#include <cstdint>

// Problem constants (fixed by the dataset)
#define BB      8
#define NG      4096
#define NO      4096

#define NBIN    256            // x micro-bins for the clustering sort
#define XLO     (-2.0f)
#define XIW     (64.0f)        // 256 bins / 4.0 span

#define OT_SIZE 128            // off-grid tile (pairs: 64)
#define N_OT    (NO / OT_SIZE) // 32
#define GT_SIZE 256            // grid tile per block (128 thr x GPT 2)
#define N_GT    (NG / GT_SIZE) // 16
#define ZS      8              // off-tile split across blocks (4 candidates each)

#define S_CUT   30.0f          // skip when min possible |s| exceeds this (w < 1e-9)
#define HL2E    0.72134752044448170f   // 0.5*log2(e)

// ---- device scratch (static; re-initialized inside kernels each launch) ----
__device__ float4 d_sxP[BB][NO/2];   // (sx_i, sx_j, sy_i, sy_j), sx=2K0*bx, sy=2K1*by
__device__ float2 d_cbP[BB][NO/2];   // (cb_i, cb_j), cb = -(K0 bx^2 + K1 by^2)
__device__ float4 d_yP [BB][NO/2];   // (y0_i, y0_j, y1_i, y1_j)
__device__ float  d_xs [BB][NO];     // sorted raw x of off points (for bounds)
__device__ float4 d_gX [BB][NG];     // (x0, x1, cA, orig_idx bits), sorted by x0
__device__ float2 d_obnd[BB][N_OT];  // off tile (xlo, xhi)
__device__ float2 d_gbnd[BB][N_GT];  // grid tile (xlo, xhi)
__device__ float2 g_partial[ZS][BB][NG];
__device__ unsigned g_tickets[BB][N_GT];   // monotonic; mod-ZS arrival test
__device__ int d_hist[BB][2][NBIN];
__device__ int d_curs[BB][2][NBIN];
__device__ int d_offs[BB][2][NBIN];

// ---- packed f32x2 helpers (sm_100+, .b64 operands) ----
__device__ __forceinline__ uint64_t pk2(float lo, float hi) {
    uint64_t r; asm("mov.b64 %0, {%1,%2};" : "=l"(r) : "f"(lo), "f"(hi)); return r;
}
__device__ __forceinline__ void unpk2(uint64_t v, float& lo, float& hi) {
    asm("mov.b64 {%0,%1}, %2;" : "=f"(lo), "=f"(hi) : "l"(v));
}
__device__ __forceinline__ uint64_t add2(uint64_t a, uint64_t b) {
    uint64_t r; asm("add.rn.f32x2 %0, %1, %2;" : "=l"(r) : "l"(a), "l"(b)); return r;
}
__device__ __forceinline__ uint64_t fma2(uint64_t a, uint64_t b, uint64_t c) {
    uint64_t r; asm("fma.rn.f32x2 %0, %1, %2, %3;" : "=l"(r) : "l"(a), "l"(b), "l"(c)); return r;
}
__device__ __forceinline__ float ex2(float x) {
    float r; asm("ex2.approx.ftz.f32 %0, %1;" : "=f"(r) : "f"(x)); return r;
}

__device__ __forceinline__ int xbin(float x) {
    float fb = fminf((float)(NBIN - 1), fmaxf(0.f, floorf((x - XLO) * XIW)));
    return (int)fb;
}

// ================= K1: cluster-sort both point sets by x ===================
__global__ void __launch_bounds__(256) prep_kernel(
    const float* __restrict__ xo, const float* __restrict__ yo,
    const float* __restrict__ xg, const float* __restrict__ lsp)
{
    __shared__ int sc[NBIN];
    __shared__ int sh[NBIN];
    const int b = blockIdx.x, tid = threadIdx.x;

    // zero per-launch state
    for (int i = tid; i < NBIN; i += 256) {
        d_hist[b][0][i] = 0; d_hist[b][1][i] = 0;
        d_curs[b][0][i] = 0; d_curs[b][1][i] = 0;
    }
    __syncthreads();

    const float ls0 = 1e-5f + log1pf(expf(lsp[0]));
    const float ls1 = 1e-5f + log1pf(expf(lsp[1]));
    const float K0 = HL2E / (ls0 * ls0);
    const float K1v = HL2E / (ls1 * ls1);

    // histograms
    for (int i = tid; i < NO; i += 256)
        atomicAdd(&d_hist[b][0][xbin(xo[((size_t)b * NO + i) * 2])], 1);
    for (int i = tid; i < NG; i += 256)
        atomicAdd(&d_hist[b][1][xbin(xg[((size_t)b * NG + i) * 2])], 1);
    __syncthreads();

    // exclusive scans (256 threads == NBIN)
    for (int a = 0; a < 2; a++) {
        int h = d_hist[b][a][tid];
        sc[tid] = h; sh[tid] = h;
        __syncthreads();
        for (int off = 1; off < NBIN; off <<= 1) {
            int v = (tid >= off) ? sc[tid - off] : 0;
            __syncthreads();
            sc[tid] += v;
            __syncthreads();
        }
        d_offs[b][a][tid] = sc[tid] - sh[tid];
        __syncthreads();
    }

    // scatter off points, prescaled, pair-interleaved
    for (int i = tid; i < NO; i += 256) {
        float bx = xo[((size_t)b * NO + i) * 2];
        float by = xo[((size_t)b * NO + i) * 2 + 1];
        float y0 = yo[((size_t)b * NO + i) * 2];
        float y1 = yo[((size_t)b * NO + i) * 2 + 1];
        int bin = xbin(bx);
        int pos = d_offs[b][0][bin] + atomicAdd(&d_curs[b][0][bin], 1);
        int pr = pos >> 1, ln = pos & 1;
        float* sp = (float*)&d_sxP[b][pr];
        sp[ln]     = 2.f * K0 * bx;
        sp[2 + ln] = 2.f * K1v * by;
        ((float*)&d_cbP[b][pr])[ln] = -(K0 * bx * bx + K1v * by * by);
        float* yp = (float*)&d_yP[b][pr];
        yp[ln]     = y0;
        yp[2 + ln] = y1;
        d_xs[b][pos] = bx;
    }
    // scatter grid points
    for (int i = tid; i < NG; i += 256) {
        float x0 = xg[((size_t)b * NG + i) * 2];
        float x1 = xg[((size_t)b * NG + i) * 2 + 1];
        int bin = xbin(x0);
        int pos = d_offs[b][1][bin] + atomicAdd(&d_curs[b][1][bin], 1);
        d_gX[b][pos] = make_float4(x0, x1, -(K0 * x0 * x0 + K1v * x1 * x1),
                                   __int_as_float(i));
    }
}

// ================= K2: tile x-bounds ===================
__global__ void __launch_bounds__(128) bounds_kernel() {
    const int b = blockIdx.y, t = blockIdx.x, tid = threadIdx.x;
    float lo, hi;
    if (t < N_OT) {
        float v = d_xs[b][t * OT_SIZE + tid];   // 128 threads = 128 values
        lo = v; hi = v;
    } else {
        int gt = t - N_OT;
        float v0 = d_gX[b][gt * GT_SIZE + tid].x;
        float v1 = d_gX[b][gt * GT_SIZE + 128 + tid].x;
        lo = fminf(v0, v1); hi = fmaxf(v0, v1);
    }
    for (int o = 16; o; o >>= 1) {
        lo = fminf(lo, __shfl_xor_sync(0xffffffffu, lo, o));
        hi = fmaxf(hi, __shfl_xor_sync(0xffffffffu, hi, o));
    }
    __shared__ float slo[4], shi[4];
    if ((tid & 31) == 0) { slo[tid >> 5] = lo; shi[tid >> 5] = hi; }
    __syncthreads();
    if (tid == 0) {
        lo = fminf(fminf(slo[0], slo[1]), fminf(slo[2], slo[3]));
        hi = fmaxf(fmaxf(shi[0], shi[1]), fmaxf(shi[2], shi[3]));
        if (t < N_OT) d_obnd[b][t] = make_float2(lo, hi);
        else          d_gbnd[b][t - N_OT] = make_float2(lo, hi);
    }
}

// ================= K3: main conv with tile skipping ===================
__global__ void __launch_bounds__(128) conv_main(
    const float* __restrict__ yg,    // [B, NG, 2] (original order)
    const float* __restrict__ lsp,
    float* __restrict__ out)
{
    __shared__ float4 ssx[OT_SIZE / 2];
    __shared__ float2 scb[OT_SIZE / 2];
    __shared__ float4 syy[OT_SIZE / 2];
    __shared__ int    s_do_reduce;

    const int gt = blockIdx.x, b = blockIdx.y, z = blockIdx.z;
    const int tid = threadIdx.x;

    const float ls0 = 1e-5f + log1pf(expf(lsp[0]));
    const float K0 = HL2E / (ls0 * ls0);

    // this thread's two grid points (same tile -> same skip set)
    const int pos0 = gt * GT_SIZE + tid;
    const int pos1 = pos0 + 128;
    float4 gv0 = d_gX[b][pos0];
    float4 gv1 = d_gX[b][pos1];
    const uint64_t a00_0 = pk2(gv0.x, gv0.x);
    const uint64_t a11_0 = pk2(gv0.y, gv0.y);
    const uint64_t cA2_0 = pk2(gv0.z, gv0.z);
    const uint64_t a00_1 = pk2(gv1.x, gv1.x);
    const uint64_t a11_1 = pk2(gv1.y, gv1.y);
    const uint64_t cA2_1 = pk2(gv1.z, gv1.z);

    uint64_t p00 = 0ull, p01 = 0ull, p10 = 0ull, p11 = 0ull;

    uint32_t usx, ucb, uyy;
    asm("{ .reg .u64 t; cvta.to.shared.u64 t, %1; cvt.u32.u64 %0, t; }"
        : "=r"(usx) : "l"((const void*)ssx));
    asm("{ .reg .u64 t; cvta.to.shared.u64 t, %1; cvt.u32.u64 %0, t; }"
        : "=r"(ucb) : "l"((const void*)scb));
    asm("{ .reg .u64 t; cvta.to.shared.u64 t, %1; cvt.u32.u64 %0, t; }"
        : "=r"(uyy) : "l"((const void*)syy));

    const float2 gbd = d_gbnd[b][gt];

    for (int c = 0; c < N_OT / ZS; c++) {
        const int ot = z + c * ZS;
        float2 obd = d_obnd[b][ot];
        float gap = fmaxf(0.f, fmaxf(obd.x - gbd.y, gbd.x - obd.y));
        if (K0 * gap * gap > S_CUT) continue;   // block-uniform branch

        __syncthreads();   // prior tile fully consumed before overwrite
        if (tid < 64) {
            ssx[tid] = d_sxP[b][ot * 64 + tid];
            scb[tid] = d_cbP[b][ot * 64 + tid];
        } else {
            syy[tid - 64] = d_yP[b][ot * 64 + tid - 64];
        }
        __syncthreads();

#pragma unroll 8
        for (int m = 0; m < OT_SIZE / 2; m++) {
            uint64_t bx2, by2, cb2, y02, y12;
            asm("ld.shared.v2.b64 {%0,%1}, [%2];"
                : "=l"(bx2), "=l"(by2) : "r"(usx + m * 16));
            asm("ld.shared.b64 %0, [%1];"
                : "=l"(cb2) : "r"(ucb + m * 8));
            asm("ld.shared.v2.b64 {%0,%1}, [%2];"
                : "=l"(y02), "=l"(y12) : "r"(uyy + m * 16));

            // grid point 0
            uint64_t s0 = fma2(bx2, a00_0, cb2);
            s0 = fma2(by2, a11_0, s0);
            s0 = add2(s0, cA2_0);
            float si, sj;
            unpk2(s0, si, sj);
            uint64_t w0 = pk2(ex2(si), ex2(sj));
            p00 = fma2(w0, y02, p00);
            p01 = fma2(w0, y12, p01);

            // grid point 1
            uint64_t s1 = fma2(bx2, a00_1, cb2);
            s1 = fma2(by2, a11_1, s1);
            s1 = add2(s1, cA2_1);
            unpk2(s1, si, sj);
            uint64_t w1 = pk2(ex2(si), ex2(sj));
            p10 = fma2(w1, y02, p10);
            p11 = fma2(w1, y12, p11);
        }
    }

    {
        float e, o, e1, o1;
        unpk2(p00, e, o);  unpk2(p01, e1, o1);
        g_partial[z][b][pos0] = make_float2(e + o, e1 + o1);
        unpk2(p10, e, o);  unpk2(p11, e1, o1);
        g_partial[z][b][pos1] = make_float2(e + o, e1 + o1);
    }

    // ---- fused reduction: last-arriving z for this (b, gt) reduces ----
    __threadfence();
    if (tid == 0) {
        unsigned old = atomicAdd(&g_tickets[b][gt], 1u);
        s_do_reduce = ((old % ZS) == ZS - 1);
    }
    __syncthreads();
    if (!s_do_reduce) return;
    __threadfence();

    float4* outy = (float4*)(out + (size_t)BB * NG * 2);
#pragma unroll
    for (int k = 0; k < 2; k++) {
        int pos = (k == 0) ? pos0 : pos1;
        float4 gv = (k == 0) ? gv0 : gv1;
        int gorig = __float_as_int(gv.w);

        ((float2*)out)[(size_t)b * NG + gorig] = make_float2(gv.x, gv.y);
        float2 yon = ((const float2*)yg)[(size_t)b * NG + gorig];

        float sxr = 0.f, syr = 0.f;
#pragma unroll
        for (int p = 0; p < ZS; p++) {   // fixed order
            float2 v = g_partial[p][b][pos];
            sxr += v.x;
            syr += v.y;
        }
        outy[(size_t)b * NG + gorig] = make_float4(yon.x, yon.y, sxr, syr);
    }
}

extern "C" void kernel_launch(void* const* d_in, const int* in_sizes, int n_in,
                              void* d_out, int out_size) {
    const float* xo  = (const float*)d_in[0];  // xc_off_grid
    const float* yo  = (const float*)d_in[1];  // yc_off_grid
    const float* xg  = (const float*)d_in[2];  // xc_on_grid
    const float* yg  = (const float*)d_in[3];  // yc_on_grid
    const float* lsp = (const float*)d_in[4];  // lengthscale_param

    prep_kernel<<<BB, 256>>>(xo, yo, xg, lsp);
    bounds_kernel<<<dim3(N_OT + N_GT, BB), 128>>>();
    conv_main<<<dim3(N_GT, BB, ZS), 128>>>(yg, lsp, (float*)d_out);
}

// round 12
// speedup vs baseline: 1.6398x; 1.6398x over previous
#include <cuda_runtime.h>
#include <cstdint>

// Problem constants (fixed by the dataset)
#define BB      8
#define NG      4096
#define NO      4096

#define NBIN    256            // x micro-bins for the clustering sort
#define XLO     (-2.0f)
#define XIW     (64.0f)        // 256 bins / 4.0 span

#define OT_SIZE 128            // off-grid tile (pairs: 64)
#define N_OT    (NO / OT_SIZE) // 32
#define GT_SIZE 256            // grid tile per block (128 thr x GPT 2)
#define N_GT    (NG / GT_SIZE) // 16
#define ZS      8              // off-tile split across blocks (4 candidates each)

#define S_CUT   30.0f          // skip when min possible |s| exceeds this (w < 1e-9)
#define HL2E    0.72134752044448170f   // 0.5*log2(e)

// ---- device scratch (static; re-initialized inside kernels each launch) ----
__device__ float4 d_sxP[BB][NO/2];   // (sx_i, sx_j, sy_i, sy_j), sx=2K0*bx, sy=2K1*by
__device__ float2 d_cbP[BB][NO/2];   // (cb_i, cb_j), cb = -(K0 bx^2 + K1 by^2)
__device__ float4 d_yP [BB][NO/2];   // (y0_i, y0_j, y1_i, y1_j)
__device__ float  d_xs [BB][NO];     // sorted raw x of off points (for bounds)
__device__ float4 d_gX [BB][NG];     // (x0, x1, cA, orig_idx bits), sorted by x0
__device__ float2 d_obnd[BB][N_OT];  // off tile (xlo, xhi)
__device__ float2 d_gbnd[BB][N_GT];  // grid tile (xlo, xhi)
__device__ float2 g_partial[ZS][BB][NG];
__device__ unsigned g_tickets[BB][N_GT];   // monotonic; mod-ZS arrival test
__device__ int d_hist[BB][2][NBIN];
__device__ int d_curs[BB][2][NBIN];
__device__ int d_offs[BB][2][NBIN];

// ---- packed f32x2 helpers (sm_100+, .b64 operands) ----
__device__ __forceinline__ uint64_t pk2(float lo, float hi) {
    uint64_t r; asm("mov.b64 %0, {%1,%2};" : "=l"(r) : "f"(lo), "f"(hi)); return r;
}
__device__ __forceinline__ void unpk2(uint64_t v, float& lo, float& hi) {
    asm("mov.b64 {%0,%1}, %2;" : "=f"(lo), "=f"(hi) : "l"(v));
}
__device__ __forceinline__ uint64_t add2(uint64_t a, uint64_t b) {
    uint64_t r; asm("add.rn.f32x2 %0, %1, %2;" : "=l"(r) : "l"(a), "l"(b)); return r;
}
__device__ __forceinline__ uint64_t fma2(uint64_t a, uint64_t b, uint64_t c) {
    uint64_t r; asm("fma.rn.f32x2 %0, %1, %2, %3;" : "=l"(r) : "l"(a), "l"(b), "l"(c)); return r;
}
__device__ __forceinline__ float ex2(float x) {
    float r; asm("ex2.approx.ftz.f32 %0, %1;" : "=f"(r) : "f"(x)); return r;
}

__device__ __forceinline__ int xbin(float x) {
    float fb = fminf((float)(NBIN - 1), fmaxf(0.f, floorf((x - XLO) * XIW)));
    return (int)fb;
}

// ============ K0: zero histograms ============
__global__ void __launch_bounds__(256) zero_kernel() {
    const int b = blockIdx.x;
    d_hist[b][0][threadIdx.x] = 0;
    d_hist[b][1][threadIdx.x] = 0;
}

// ============ K1a: histograms (wide: 16 blocks/batch) ============
__global__ void __launch_bounds__(256) hist_kernel(
    const float* __restrict__ xo, const float* __restrict__ xg)
{
    const int b = blockIdx.y;
    const int i = blockIdx.x * 256 + threadIdx.x;    // 16*256 = 4096
    atomicAdd(&d_hist[b][0][xbin(xo[((size_t)b * NO + i) * 2])], 1);
    atomicAdd(&d_hist[b][1][xbin(xg[((size_t)b * NG + i) * 2])], 1);
}

// ============ K1b: exclusive scans + cursor reset ============
__global__ void __launch_bounds__(256) scan_kernel() {
    __shared__ int sc[NBIN];
    const int b = blockIdx.x, tid = threadIdx.x;
    d_curs[b][0][tid] = 0;
    d_curs[b][1][tid] = 0;
#pragma unroll
    for (int a = 0; a < 2; a++) {
        int h = d_hist[b][a][tid];
        sc[tid] = h;
        __syncthreads();
        for (int off = 1; off < NBIN; off <<= 1) {
            int v = (tid >= off) ? sc[tid - off] : 0;
            __syncthreads();
            sc[tid] += v;
            __syncthreads();
        }
        d_offs[b][a][tid] = sc[tid] - h;
        __syncthreads();
    }
}

// ============ K1c: scatter (wide: 16 blocks/batch) ============
__global__ void __launch_bounds__(256) scatter_kernel(
    const float* __restrict__ xo, const float* __restrict__ yo,
    const float* __restrict__ xg, const float* __restrict__ lsp)
{
    const int b = blockIdx.y;
    const int i = blockIdx.x * 256 + threadIdx.x;    // one off + one grid point

    const float ls0 = 1e-5f + log1pf(expf(lsp[0]));
    const float ls1 = 1e-5f + log1pf(expf(lsp[1]));
    const float K0 = HL2E / (ls0 * ls0);
    const float K1v = HL2E / (ls1 * ls1);

    // off point
    {
        float bx = xo[((size_t)b * NO + i) * 2];
        float by = xo[((size_t)b * NO + i) * 2 + 1];
        float y0 = yo[((size_t)b * NO + i) * 2];
        float y1 = yo[((size_t)b * NO + i) * 2 + 1];
        int bin = xbin(bx);
        int pos = d_offs[b][0][bin] + atomicAdd(&d_curs[b][0][bin], 1);
        int pr = pos >> 1, ln = pos & 1;
        float* sp = (float*)&d_sxP[b][pr];
        sp[ln]     = 2.f * K0 * bx;
        sp[2 + ln] = 2.f * K1v * by;
        ((float*)&d_cbP[b][pr])[ln] = -(K0 * bx * bx + K1v * by * by);
        float* yp = (float*)&d_yP[b][pr];
        yp[ln]     = y0;
        yp[2 + ln] = y1;
        d_xs[b][pos] = bx;
    }
    // grid point
    {
        float x0 = xg[((size_t)b * NG + i) * 2];
        float x1 = xg[((size_t)b * NG + i) * 2 + 1];
        int bin = xbin(x0);
        int pos = d_offs[b][1][bin] + atomicAdd(&d_curs[b][1][bin], 1);
        d_gX[b][pos] = make_float4(x0, x1, -(K0 * x0 * x0 + K1v * x1 * x1),
                                   __int_as_float(i));
    }
}

// ================= K2: tile x-bounds ===================
__global__ void __launch_bounds__(128) bounds_kernel() {
    const int b = blockIdx.y, t = blockIdx.x, tid = threadIdx.x;
    float lo, hi;
    if (t < N_OT) {
        float v = d_xs[b][t * OT_SIZE + tid];   // 128 threads = 128 values
        lo = v; hi = v;
    } else {
        int gt = t - N_OT;
        float v0 = d_gX[b][gt * GT_SIZE + tid].x;
        float v1 = d_gX[b][gt * GT_SIZE + 128 + tid].x;
        lo = fminf(v0, v1); hi = fmaxf(v0, v1);
    }
    for (int o = 16; o; o >>= 1) {
        lo = fminf(lo, __shfl_xor_sync(0xffffffffu, lo, o));
        hi = fmaxf(hi, __shfl_xor_sync(0xffffffffu, hi, o));
    }
    __shared__ float slo[4], shi[4];
    if ((tid & 31) == 0) { slo[tid >> 5] = lo; shi[tid >> 5] = hi; }
    __syncthreads();
    if (tid == 0) {
        lo = fminf(fminf(slo[0], slo[1]), fminf(slo[2], slo[3]));
        hi = fmaxf(fmaxf(shi[0], shi[1]), fmaxf(shi[2], shi[3]));
        if (t < N_OT) d_obnd[b][t] = make_float2(lo, hi);
        else          d_gbnd[b][t - N_OT] = make_float2(lo, hi);
    }
}

// ================= K3: main conv with tile skipping ===================
__global__ void __launch_bounds__(128) conv_main(
    const float* __restrict__ yg,    // [B, NG, 2] (original order)
    const float* __restrict__ lsp,
    float* __restrict__ out)
{
    __shared__ float4 ssx[OT_SIZE / 2];
    __shared__ float2 scb[OT_SIZE / 2];
    __shared__ float4 syy[OT_SIZE / 2];
    __shared__ int    s_do_reduce;

    const int gt = blockIdx.x, b = blockIdx.y, z = blockIdx.z;
    const int tid = threadIdx.x;

    const float ls0 = 1e-5f + log1pf(expf(lsp[0]));
    const float K0 = HL2E / (ls0 * ls0);

    // this thread's two grid points (same tile -> same skip set)
    const int pos0 = gt * GT_SIZE + tid;
    const int pos1 = pos0 + 128;
    float4 gv0 = d_gX[b][pos0];
    float4 gv1 = d_gX[b][pos1];
    const uint64_t a00_0 = pk2(gv0.x, gv0.x);
    const uint64_t a11_0 = pk2(gv0.y, gv0.y);
    const uint64_t cA2_0 = pk2(gv0.z, gv0.z);
    const uint64_t a00_1 = pk2(gv1.x, gv1.x);
    const uint64_t a11_1 = pk2(gv1.y, gv1.y);
    const uint64_t cA2_1 = pk2(gv1.z, gv1.z);

    uint64_t p00 = 0ull, p01 = 0ull, p10 = 0ull, p11 = 0ull;

    uint32_t usx, ucb, uyy;
    asm("{ .reg .u64 t; cvta.to.shared.u64 t, %1; cvt.u32.u64 %0, t; }"
        : "=r"(usx) : "l"((const void*)ssx));
    asm("{ .reg .u64 t; cvta.to.shared.u64 t, %1; cvt.u32.u64 %0, t; }"
        : "=r"(ucb) : "l"((const void*)scb));
    asm("{ .reg .u64 t; cvta.to.shared.u64 t, %1; cvt.u32.u64 %0, t; }"
        : "=r"(uyy) : "l"((const void*)syy));

    const float2 gbd = d_gbnd[b][gt];

    for (int c = 0; c < N_OT / ZS; c++) {
        const int ot = z + c * ZS;
        float2 obd = d_obnd[b][ot];
        float gap = fmaxf(0.f, fmaxf(obd.x - gbd.y, gbd.x - obd.y));
        if (K0 * gap * gap > S_CUT) continue;   // block-uniform branch

        __syncthreads();   // prior tile fully consumed before overwrite
        if (tid < 64) {
            ssx[tid] = d_sxP[b][ot * 64 + tid];
            scb[tid] = d_cbP[b][ot * 64 + tid];
        } else {
            syy[tid - 64] = d_yP[b][ot * 64 + tid - 64];
        }
        __syncthreads();

#pragma unroll 8
        for (int m = 0; m < OT_SIZE / 2; m++) {
            uint64_t bx2, by2, cb2, y02, y12;
            asm("ld.shared.v2.b64 {%0,%1}, [%2];"
                : "=l"(bx2), "=l"(by2) : "r"(usx + m * 16));
            asm("ld.shared.b64 %0, [%1];"
                : "=l"(cb2) : "r"(ucb + m * 8));
            asm("ld.shared.v2.b64 {%0,%1}, [%2];"
                : "=l"(y02), "=l"(y12) : "r"(uyy + m * 16));

            // grid point 0
            uint64_t s0 = fma2(bx2, a00_0, cb2);
            s0 = fma2(by2, a11_0, s0);
            s0 = add2(s0, cA2_0);
            float si, sj;
            unpk2(s0, si, sj);
            uint64_t w0 = pk2(ex2(si), ex2(sj));
            p00 = fma2(w0, y02, p00);
            p01 = fma2(w0, y12, p01);

            // grid point 1
            uint64_t s1 = fma2(bx2, a00_1, cb2);
            s1 = fma2(by2, a11_1, s1);
            s1 = add2(s1, cA2_1);
            unpk2(s1, si, sj);
            uint64_t w1 = pk2(ex2(si), ex2(sj));
            p10 = fma2(w1, y02, p10);
            p11 = fma2(w1, y12, p11);
        }
    }

    {
        float e, o, e1, o1;
        unpk2(p00, e, o);  unpk2(p01, e1, o1);
        g_partial[z][b][pos0] = make_float2(e + o, e1 + o1);
        unpk2(p10, e, o);  unpk2(p11, e1, o1);
        g_partial[z][b][pos1] = make_float2(e + o, e1 + o1);
    }

    // ---- fused reduction: last-arriving z for this (b, gt) reduces ----
    __threadfence();
    if (tid == 0) {
        unsigned old = atomicAdd(&g_tickets[b][gt], 1u);
        s_do_reduce = ((old % ZS) == ZS - 1);
    }
    __syncthreads();
    if (!s_do_reduce) return;
    __threadfence();

    float4* outy = (float4*)(out + (size_t)BB * NG * 2);
#pragma unroll
    for (int k = 0; k < 2; k++) {
        int pos = (k == 0) ? pos0 : pos1;
        float4 gv = (k == 0) ? gv0 : gv1;
        int gorig = __float_as_int(gv.w);

        ((float2*)out)[(size_t)b * NG + gorig] = make_float2(gv.x, gv.y);
        float2 yon = ((const float2*)yg)[(size_t)b * NG + gorig];

        float sxr = 0.f, syr = 0.f;
#pragma unroll
        for (int p = 0; p < ZS; p++) {   // fixed order
            float2 v = g_partial[p][b][pos];
            sxr += v.x;
            syr += v.y;
        }
        outy[(size_t)b * NG + gorig] = make_float4(yon.x, yon.y, sxr, syr);
    }
}

extern "C" void kernel_launch(void* const* d_in, const int* in_sizes, int n_in,
                              void* d_out, int out_size) {
    const float* xo  = (const float*)d_in[0];  // xc_off_grid
    const float* yo  = (const float*)d_in[1];  // yc_off_grid
    const float* xg  = (const float*)d_in[2];  // xc_on_grid
    const float* yg  = (const float*)d_in[3];  // yc_on_grid
    const float* lsp = (const float*)d_in[4];  // lengthscale_param

    zero_kernel<<<BB, 256>>>();
    hist_kernel<<<dim3(16, BB), 256>>>(xo, xg);
    scan_kernel<<<BB, 256>>>();
    scatter_kernel<<<dim3(16, BB), 256>>>(xo, yo, xg, lsp);
    bounds_kernel<<<dim3(N_OT + N_GT, BB), 128>>>();
    conv_main<<<dim3(N_GT, BB, ZS), 128>>>(yg, lsp, (float*)d_out);
}